// round 3
// baseline (speedup 1.0000x reference)
#include <cuda_runtime.h>
#include <cuda_bf16.h>

// CTC batch cost (Keras ctc_batch_cost semantics, full lengths).
// B=64, T=2048, C=128 (blank = C-1 = 127), L=256, S = 2L+1 = 513.
//
// Mapping: 1 CTA per batch element, 512 threads; thread tid owns state tid
// (tid 0 also owns state 512). Forward recurrence runs entirely in the
// log2 domain so exp/log are single MUFU instructions (EX2 / LG2);
// converted to natural log only for the final output.
//
// Per step:
//   - all threads: alpha update (lse3 in base-2 + logp gather from shared)
//   - threads < 128: convert prefetched frame t+1 into lp buffer,
//     issue LDG for frame t+5 (prefetch distance 4 steps hides DRAM latency)
//   - one __syncthreads
// alpha and lp are double-buffered in shared memory.
//
// NOTE: y_true is int32 (JAX x64 is disabled; jnp.int64 downcasts to int32).

#define CTC_B 64
#define CTC_T 2048
#define CTC_C 128
#define CTC_L 256
#define CTC_S 513          // 2L+1
#define NEGF (-1e30f)
#define EPSF (1e-7f)
#define LN2F (0.69314718055994530942f)

__device__ __forceinline__ float ex2f_(float x) {
    float r;
    asm("ex2.approx.ftz.f32 %0, %1;" : "=f"(r) : "f"(x));
    return r;
}
__device__ __forceinline__ float lg2f_(float x) {
    float r;
    asm("lg2.approx.ftz.f32 %0, %1;" : "=f"(r) : "f"(x));
    return r;
}

__global__ __launch_bounds__(512, 1)
void ctc_forward_kernel(const int* __restrict__ y_true,
                        const float* __restrict__ y_pred,
                        float* __restrict__ out) {
    const int b   = blockIdx.x;
    const int tid = threadIdx.x;

    __shared__ float s_alpha[2][CTC_S + 2];  // state s stored at index s+2; [0],[1] = NEG pads
    __shared__ float s_lp[2][CTC_C];         // log2(y_pred[t] + eps), double buffered
    __shared__ int   s_ext[CTC_S];           // bits[6:0] = class, bit 8 = skip-allowed

    const int*   lab = y_true + b * CTC_L;
    const float* Y   = y_pred + (size_t)b * CTC_T * CTC_C;

    // ---- build extended label sequence + skip mask ----
    for (int s = tid; s < CTC_S; s += 512) {
        int cls, skip;
        if (s & 1) {
            int i = s >> 1;
            cls  = lab[i] & 127;
            skip = (s >= 3 && cls != (lab[i - 1] & 127)) ? 1 : 0;
        } else {
            cls  = CTC_C - 1;  // blank
            skip = 0;
        }
        s_ext[s] = cls | (skip << 8);
    }

    // ---- init alpha buffers to NEG (both, incl. pads) ----
    for (int s = tid; s < CTC_S + 2; s += 512) {
        s_alpha[0][s] = NEGF;
        s_alpha[1][s] = NEGF;
    }
    __syncthreads();

    // alpha0: state 0 = blank at t=0, state 1 = label0 at t=0
    if (tid == 0) s_alpha[0][2] = lg2f_(Y[CTC_C - 1] + EPSF);
    if (tid == 1) s_alpha[0][3] = lg2f_(Y[lab[0] & 127] + EPSF);

    // ---- prologue: lp for frame 1, prefetch frames 2..5 ----
    float r0 = 0.f, r1 = 0.f, r2 = 0.f, r3 = 0.f;
    if (tid < CTC_C) {
        s_lp[1][tid] = lg2f_(Y[CTC_C + tid] + EPSF);
        r0 = Y[2 * CTC_C + tid];
        r1 = Y[3 * CTC_C + tid];
        r2 = Y[4 * CTC_C + tid];
        r3 = Y[5 * CTC_C + tid];
    }
    __syncthreads();

    // clamped frame load (frames >= T are never consumed, just keeps pipeline uniform)
#define LOADF(t) Y[(size_t)((t) < CTC_T ? (t) : (CTC_T - 1)) * CTC_C + tid]

#define STEP(t, r) do {                                                        \
        const float* __restrict__ ap  = s_alpha[((t) + 1) & 1];                \
        float*       __restrict__ an  = s_alpha[(t) & 1];                      \
        const float* __restrict__ lpc = s_lp[(t) & 1];                         \
        for (int s = tid; s < CTC_S; s += 512) {                               \
            int   e   = s_ext[s];                                              \
            float av  = ap[s + 2];                                             \
            float bv  = ap[s + 1];                                             \
            float cv  = (e & 256) ? ap[s] : NEGF;                              \
            float lpv = lpc[e & 127];                                          \
            float m   = fmaxf(av, fmaxf(bv, cv));                              \
            float sum = ex2f_(av - m) + ex2f_(bv - m) + ex2f_(cv - m);         \
            an[s + 2] = m + lg2f_(sum) + lpv;                                  \
        }                                                                      \
        if (tid < CTC_C) {                                                     \
            s_lp[((t) + 1) & 1][tid] = lg2f_((r) + EPSF);                      \
            (r) = LOADF((t) + 5);                                              \
        }                                                                      \
        __syncthreads();                                                       \
    } while (0)

    // ---- main recurrence: t = 1 .. T-1 (2047 steps), unrolled by 4 ----
    int t = 1;
    for (; t + 3 <= CTC_T - 1; t += 4) {
        STEP(t,     r0);
        STEP(t + 1, r1);
        STEP(t + 2, r2);
        STEP(t + 3, r3);
    }
    // remainder: t = 2045, 2046, 2047
    STEP(CTC_T - 3, r0);
    STEP(CTC_T - 2, r1);
    STEP(CTC_T - 1, r2);

#undef STEP
#undef LOADF

    // final alpha lives in buffer (T-1)&1 = 1
    if (tid == 0) {
        float a = s_alpha[1][CTC_S - 1 + 2];  // state S-1
        float c = s_alpha[1][CTC_S - 2 + 2];  // state S-2
        float m = fmaxf(a, c);
        float l2 = m + lg2f_(ex2f_(a - m) + ex2f_(c - m));
        out[b] = -l2 * LN2F;  // convert log2 -> ln
    }
}

extern "C" void kernel_launch(void* const* d_in, const int* in_sizes, int n_in,
                              void* d_out, int out_size) {
    // Identify inputs by element count: y_true has B*L = 16384, y_pred has B*T*C.
    const int*   y_true;
    const float* y_pred;
    if (in_sizes[0] == CTC_B * CTC_L) {
        y_true = (const int*)d_in[0];
        y_pred = (const float*)d_in[1];
    } else {
        y_true = (const int*)d_in[1];
        y_pred = (const float*)d_in[0];
    }
    float* out = (float*)d_out;

    ctc_forward_kernel<<<CTC_B, 512>>>(y_true, y_pred, out);
}

// round 4
// speedup vs baseline: 1.9420x; 1.9420x over previous
#include <cuda_runtime.h>
#include <cstdint>

// CTC batch cost (Keras ctc_batch_cost, full lengths).
// B=64, T=2048, C=128 (blank=127), L=256, S=2L+1=513.
//
// 2-CTA cluster per batch (128 CTAs -> ~128 SMs busy vs 64 before).
// CTC forward deps are one-directional (alpha[s] <- alpha[s-2..s]), so:
//   rank0 owns states [0,272)   -- never needs rank1's data
//   rank1 owns states [272,513) -- computes halo [240,272) redundantly;
//     halo decays 2 states/step, refreshed from rank0 every 16 steps via
//     st.shared::cluster + one cluster barrier (amortized ~30 cyc/step).
// Log2-domain lse3 (3x EX2 + 1x LG2 on MUFU), shared double-buffered alpha,
// frame prefetch distance 4 hides DRAM latency. y_true is int32.

#define CTC_B 64
#define CTC_T 2048
#define CTC_C 128
#define CTC_L 256
#define CTC_S 513
#define NEGF (-1e30f)
#define EPSF (1e-7f)
#define LN2F (0.69314718055994530942f)

#define SPLIT   272     // rank0 owns [0,272), rank1 owns [272,513)
#define HALO    32      // rank1 redundant states [240,272)
#define NTHR    288     // 9 warps
#define ALPHA_N 284     // 2 left pads + up to idx 275 + dummy slot 278

__device__ __forceinline__ float ex2f_(float x) {
    float r; asm("ex2.approx.ftz.f32 %0, %1;" : "=f"(r) : "f"(x)); return r;
}
__device__ __forceinline__ float lg2f_(float x) {
    float r; asm("lg2.approx.ftz.f32 %0, %1;" : "=f"(r) : "f"(x)); return r;
}
__device__ __forceinline__ uint32_t smem_u32_(const void* p) {
    uint32_t a;
    asm("{ .reg .u64 t; cvta.to.shared.u64 t, %1; cvt.u32.u64 %0, t; }"
        : "=r"(a) : "l"(p));
    return a;
}

__global__ __launch_bounds__(NTHR, 1) __cluster_dims__(2, 1, 1)
void ctc_forward_kernel(const int* __restrict__ y_true,
                        const float* __restrict__ y_pred,
                        float* __restrict__ out) {
    __shared__ float s_alpha[2][ALPHA_N];
    __shared__ float s_lp[2][CTC_C];
    __shared__ float s_halo[2][HALO];

    const int tid = threadIdx.x;
    uint32_t rank;
    asm("mov.u32 %0, %%cluster_ctarank;" : "=r"(rank));
    const int b = blockIdx.x >> 1;

    const int*   lab = y_true + b * CTC_L;
    const float* Y   = y_pred + (size_t)b * CTC_T * CTC_C;

    // ---- per-thread static state ----
    const int  s      = (rank == 0) ? tid : 240 + tid;
    const bool active = (rank == 0) ? (tid < SPLIT) : (tid < 273);
    const int  ai     = active ? tid + 2 : 278;   // dummy slot for inactive

    int cls = CTC_C - 1, skip = 0;
    if (active && (s & 1)) {
        int i = s >> 1;
        cls  = lab[i] & 127;
        skip = (s >= 3 && cls != (lab[i - 1] & 127)) ? 1 : 0;
    }
    const float* lpp0 = &s_lp[0][cls];
    const float* lpp1 = &s_lp[1][cls];

    // remote mailbox addresses (used by rank0 boundary senders)
    int hj = (tid >= 240 && tid < SPLIT) ? (tid - 240) : 0;
    uint32_t rh0, rh1;
    {
        uint32_t l0 = smem_u32_(&s_halo[0][hj]);
        uint32_t l1 = smem_u32_(&s_halo[1][hj]);
        asm("mapa.shared::cluster.u32 %0, %1, %2;" : "=r"(rh0) : "r"(l0), "r"(1));
        asm("mapa.shared::cluster.u32 %0, %1, %2;" : "=r"(rh1) : "r"(l1), "r"(1));
    }

    // ---- init alpha buffers to NEG ----
    for (int i = tid; i < ALPHA_N; i += NTHR) {
        s_alpha[0][i] = NEGF;
        s_alpha[1][i] = NEGF;
    }
    __syncthreads();

    // alpha0 (buffer 0): state0 = blank@t0, state1 = label0@t0 (rank0 only;
    // all rank1 states >= 240 are NEG at t=0, already set)
    if (rank == 0 && tid == 0) s_alpha[0][2] = lg2f_(Y[CTC_C - 1] + EPSF);
    if (rank == 0 && tid == 1) s_alpha[0][3] = lg2f_(Y[lab[0] & 127] + EPSF);

    // ---- prologue: lp for frame 1, prefetch frames 2..5 ----
    float r0 = 0.f, r1 = 0.f, r2 = 0.f, r3 = 0.f;
    if (tid < CTC_C) {
        s_lp[1][tid] = lg2f_(Y[CTC_C + tid] + EPSF);
        r0 = Y[2 * CTC_C + tid];
        r1 = Y[3 * CTC_C + tid];
        r2 = Y[4 * CTC_C + tid];
        r3 = Y[5 * CTC_C + tid];
    }
    __syncthreads();

    float cur = NEGF;

#define LOADF(t) Y[(size_t)((t) < CTC_T ? (t) : (CTC_T - 1)) * CTC_C + tid]

    // CBv = (t)&1 as a literal so buffer addressing is compile-time
#define STEP(t, CBv, r) do {                                                   \
        float av  = s_alpha[1 - (CBv)][ai];                                    \
        float bv  = s_alpha[1 - (CBv)][ai - 1];                                \
        float cv  = skip ? s_alpha[1 - (CBv)][ai - 2] : NEGF;                  \
        float lpv = (CBv) ? lpp1[0] : lpp0[0];                                 \
        float m   = fmaxf(av, fmaxf(bv, cv));                                  \
        float sum = (ex2f_(av - m) + ex2f_(bv - m)) + ex2f_(cv - m);           \
        cur = (m + lpv) + lg2f_(sum);                                          \
        s_alpha[(CBv)][ai] = cur;                                              \
        if (tid < CTC_C) {                                                     \
            s_lp[1 - (CBv)][tid] = lg2f_((r) + EPSF);                          \
            (r) = LOADF((t) + 5);                                              \
        }                                                                      \
        __syncthreads();                                                       \
    } while (0)

    // ---- main recurrence: t = 1..2047, unrolled by 4; exchange every 16 ----
    for (int t = 1; t + 3 <= CTC_T - 1; t += 4) {
        STEP(t,     1, r0);
        STEP(t + 1, 0, r1);
        STEP(t + 2, 1, r2);
        STEP(t + 3, 0, r3);

        if (((t + 3) & 15) == 0) {
            // alpha at time (t+3) is in buffer 0 (t+3 is a multiple of 16)
            int buf = ((t + 3) >> 4) & 1;
            if (rank == 0 && tid >= 240 && tid < SPLIT) {
                uint32_t ra = buf ? rh1 : rh0;
                asm volatile("st.shared::cluster.f32 [%0], %1;"
                             :: "r"(ra), "f"(cur) : "memory");
            }
            asm volatile("barrier.cluster.arrive.aligned;" ::: "memory");
            asm volatile("barrier.cluster.wait.aligned;"   ::: "memory");
            if (rank == 1) {
                if (tid < HALO) s_alpha[0][tid + 2] = s_halo[buf][tid];
                __syncthreads();
            }
        }
    }
    // tail: t = 2045, 2046, 2047
    STEP(CTC_T - 3, 1, r0);
    STEP(CTC_T - 2, 0, r1);
    STEP(CTC_T - 1, 1, r2);

#undef STEP
#undef LOADF

    // final alpha (time 2047) is in buffer 1; rank1 holds states 511,512
    if (rank == 1 && tid == 0) {
        float a = s_alpha[1][512 - 240 + 2];  // state 512
        float c = s_alpha[1][511 - 240 + 2];  // state 511
        float m = fmaxf(a, c);
        float l2 = m + lg2f_(ex2f_(a - m) + ex2f_(c - m));
        out[b] = -l2 * LN2F;
    }
}

extern "C" void kernel_launch(void* const* d_in, const int* in_sizes, int n_in,
                              void* d_out, int out_size) {
    const int*   y_true;
    const float* y_pred;
    if (in_sizes[0] == CTC_B * CTC_L) {
        y_true = (const int*)d_in[0];
        y_pred = (const float*)d_in[1];
    } else {
        y_true = (const int*)d_in[1];
        y_pred = (const float*)d_in[0];
    }
    float* out = (float*)d_out;

    ctc_forward_kernel<<<2 * CTC_B, NTHR>>>(y_true, y_pred, out);
}